// round 4
// baseline (speedup 1.0000x reference)
#include <cuda_runtime.h>
#include <cuda_bf16.h>

#define NMAX 50000
#define EPS  1e-5f
#define AST  68          // row stride (floats): mult of 4 for float4, 68%32=4 spreads banks
#define PPB  16          // points per block (2 sub-batches of 8)

// ---------------- scratch (static device arrays: allocation-free) ----------
__device__ float g_q[NMAX * 64];
__device__ float g_k[NMAX * 64];
__device__ float g_v[NMAX * 64];

// ---------------- packed f32x2 helpers --------------------------------------
__device__ __forceinline__ unsigned long long pack2(float x, float y) {
    unsigned long long r;
    asm("mov.b64 %0,{%1,%2};" : "=l"(r) : "f"(x), "f"(y));
    return r;
}
__device__ __forceinline__ void fma2(unsigned long long& d, unsigned long long a, unsigned long long b) {
    asm("fma.rn.f32x2 %0,%1,%2,%0;" : "+l"(d) : "l"(a), "l"(b));
}
__device__ __forceinline__ float2 unpack2(unsigned long long v) {
    float2 f;
    asm("mov.b64 {%0,%1},%2;" : "=f"(f.x), "=f"(f.y) : "l"(v));
    return f;
}

// ======================= kernel 1: q/k/v projections ========================
// 256 rows per block; all three weight matrices staged once (48KB) + Fs tile.
#define QK_SMEM_FLOATS (3 * 4096 + 64 * 65)
#define QK_SMEM_BYTES  (QK_SMEM_FLOATS * 4)

__global__ __launch_bounds__(256) void qkv_kernel(
    const float* __restrict__ feat,
    const float* __restrict__ wq, const float* __restrict__ bq,
    const float* __restrict__ wk, const float* __restrict__ bk,
    const float* __restrict__ wv, const float* __restrict__ bv,
    int n)
{
    extern __shared__ float qsm[];
    float* Ws = qsm;             // 3 * 4096
    float* Fs = qsm + 12288;     // 64 * 65
    const int t = threadIdx.x;

    for (int i = t; i < 1024; i += 256) ((float4*)Ws)[i]        = ((const float4*)wq)[i];
    for (int i = t; i < 1024; i += 256) ((float4*)(Ws+4096))[i] = ((const float4*)wk)[i];
    for (int i = t; i < 1024; i += 256) ((float4*)(Ws+8192))[i] = ((const float4*)wv)[i];

    const float* Bm[3] = { bq, bk, bv };
    float* Om[3] = { g_q, g_k, g_v };

    const int cg = t & 7;
    const int r0 = t >> 3;
    const int c0 = cg * 8;

    for (int tile = 0; tile < 4; tile++) {
        const int row0 = blockIdx.x * 256 + tile * 64;
        __syncthreads();
        for (int i = t; i < 64 * 16; i += 256) {
            int r = i >> 4;
            int c4 = (i & 15) * 4;
            float4 f = make_float4(0.f, 0.f, 0.f, 0.f);
            if (row0 + r < n) f = *(const float4*)&feat[(row0 + r) * 64 + c4];
            Fs[r * 65 + c4 + 0] = f.x; Fs[r * 65 + c4 + 1] = f.y;
            Fs[r * 65 + c4 + 2] = f.z; Fs[r * 65 + c4 + 3] = f.w;
        }
        __syncthreads();

        #pragma unroll
        for (int m = 0; m < 3; m++) {
            const float* Wm = Ws + m * 4096;
            unsigned long long acc[2][4];
            {
                const float* b = Bm[m];
                #pragma unroll
                for (int h = 0; h < 4; h++) {
                    unsigned long long bb = pack2(__ldg(&b[c0 + 2 * h]), __ldg(&b[c0 + 2 * h + 1]));
                    acc[0][h] = bb; acc[1][h] = bb;
                }
            }
            #pragma unroll 16
            for (int k = 0; k < 64; k++) {
                float a0f = Fs[r0 * 65 + k];
                float a1f = Fs[(r0 + 32) * 65 + k];
                unsigned long long a0 = pack2(a0f, a0f);
                unsigned long long a1 = pack2(a1f, a1f);
                const ulonglong2* w = (const ulonglong2*)&Wm[k * 64 + c0];
                ulonglong2 w0 = w[0], w1 = w[1];
                fma2(acc[0][0], a0, w0.x); fma2(acc[0][1], a0, w0.y);
                fma2(acc[0][2], a0, w1.x); fma2(acc[0][3], a0, w1.y);
                fma2(acc[1][0], a1, w0.x); fma2(acc[1][1], a1, w0.y);
                fma2(acc[1][2], a1, w1.x); fma2(acc[1][3], a1, w1.y);
            }
            #pragma unroll
            for (int rr = 0; rr < 2; rr++) {
                int gr = row0 + r0 + rr * 32;
                if (gr < n) {
                    float2 p0 = unpack2(acc[rr][0]);
                    float2 p1 = unpack2(acc[rr][1]);
                    float2 p2 = unpack2(acc[rr][2]);
                    float2 p3 = unpack2(acc[rr][3]);
                    *(float4*)&Om[m][gr * 64 + c0]     = make_float4(p0.x, p0.y, p1.x, p1.y);
                    *(float4*)&Om[m][gr * 64 + c0 + 4] = make_float4(p2.x, p2.y, p3.x, p3.y);
                }
            }
        }
    }
}

// ======================= kernel 2: fused, batched-GEMM version ==============
// 128 threads. Sub-batch: 8 points => 128 rows; GEMMs 128x64x64, 8x8 register
// tiles. Warp wid owns rows [32wid, 32wid+32) in EVERY phase -> warp-local
// buffers, __syncwarp instead of __syncthreads except around s_o/epilogue.
// Phase A is cooperative: half-warp per neighbor row -> coalesced gathers.
#define SMEM_FLOATS (4096*2 + 128*AST + 128*6 + 512 + 768)
#define SMEM_BYTES  (SMEM_FLOATS * 4)

__global__ __launch_bounds__(128, 3) void fused_kernel(
    const float* __restrict__ points,
    const float* __restrict__ feat,
    const int*   __restrict__ nbr,
    const float* __restrict__ wp,  const float* __restrict__ bp,
    const float* __restrict__ gp,  const float* __restrict__ betap,
    const float* __restrict__ wg1, const float* __restrict__ bg1,
    const float* __restrict__ gg,  const float* __restrict__ betag,
    const float* __restrict__ wg2, const float* __restrict__ bg2,
    const float* __restrict__ wo,  const float* __restrict__ bo,
    float* __restrict__ outp, int n)
{
    extern __shared__ float sm[];
    float* wg1s = sm;                    // 4096
    float* wg2s = wg1s + 4096;           // 4096
    float* abuf = wg2s + 4096;           // 128*AST (attn_in, then h)
    float* s_rx = abuf + 128 * AST;      // 128
    float* s_ry = s_rx + 128;            // 128
    float* s_rz = s_ry + 128;            // 128
    float* s_mu = s_rz + 128;            // 128
    float* s_rs = s_mu + 128;            // 128
    int*   s_nb = (int*)(s_rs + 128);    // 128
    float* s_o  = (float*)(s_nb + 128);  // 512 (8 points x 64)
    float* sv   = s_o + 512;             // 768 small vectors
    // sv: [0]=bg1 [64]=gg [128]=betag [192]=bg2 [256]=bp [320]=gp [384]=betap
    //     [448]=bo [512..704)=wp rows

    const int t = threadIdx.x;

    for (int i = t; i < 1024; i += 128) ((float4*)wg1s)[i] = ((const float4*)wg1)[i];
    for (int i = t; i < 1024; i += 128) ((float4*)wg2s)[i] = ((const float4*)wg2)[i];
    if (t < 64) {
        sv[t]       = bg1[t];   sv[64 + t]  = gg[t];      sv[128 + t] = betag[t];
        sv[192 + t] = bg2[t];   sv[256 + t] = bp[t];      sv[320 + t] = gp[t];
        sv[384 + t] = betap[t]; sv[448 + t] = bo[t];
        sv[512 + t] = wp[t];    sv[576 + t] = wp[64 + t]; sv[640 + t] = wp[128 + t];
    }
    __syncthreads();

    const int wid  = t >> 5;
    const int lane = t & 31;
    const int rtl  = (t >> 3) & 3;
    const int cg   = t & 7;
    const int c0   = cg * 8;
    const int hw   = lane >> 4;       // half-warp id
    const int hh   = lane & 15;       // lane within half-warp
    const int hc4  = hh * 4;          // channel group in phase A
    int rofs[8];
    #pragma unroll
    for (int i = 0; i < 8; i++)
        rofs[i] = (wid * 32 + (i >> 2) * 16 + (i & 3) * 4 + rtl) * AST;

    for (int b = 0; b < 2; b++) {
        const int pbase = blockIdx.x * PPB + b * 8;

        // ---- phase A (cooperative): half-warp per row, coalesced gathers ---
        #pragma unroll 2
        for (int rr = 0; rr < 16; rr++) {
            const int row = wid * 32 + rr * 2 + hw;
            const int np  = pbase + (row >> 4);
            const int jn  = row & 15;
            const int npc = (np < n) ? np : 0;
            const int nb  = __ldg(&nbr[npc * 16 + jn]);

            float rx = __ldg(&points[nb * 3 + 0]) - __ldg(&points[npc * 3 + 0]);
            float ry = __ldg(&points[nb * 3 + 1]) - __ldg(&points[npc * 3 + 1]);
            float rz = __ldg(&points[nb * 3 + 2]) - __ldg(&points[npc * 3 + 2]);

            float pre[4];
            #pragma unroll
            for (int u = 0; u < 4; u++) {
                int c = hc4 + u;
                pre[u] = fmaf(rx, sv[512 + c], fmaf(ry, sv[576 + c], fmaf(rz, sv[640 + c], sv[256 + c])));
            }
            float s1 = (pre[0] + pre[1]) + (pre[2] + pre[3]);
            float s2 = fmaf(pre[0], pre[0], pre[1] * pre[1]) + fmaf(pre[2], pre[2], pre[3] * pre[3]);
            #pragma unroll
            for (int m = 1; m < 16; m <<= 1) {
                s1 += __shfl_xor_sync(0xffffffffu, s1, m);
                s2 += __shfl_xor_sync(0xffffffffu, s2, m);
            }
            float mu = s1 * 0.015625f;
            float rs = rsqrtf(s2 * 0.015625f - mu * mu + EPS);

            float4 q4  = *(const float4*)&g_q[(size_t)npc * 64 + hc4];
            float4 gk4 = *(const float4*)&g_k[(size_t)nb * 64 + hc4];
            float4 o;
            #pragma unroll
            for (int u = 0; u < 4; u++) {
                int c = hc4 + u;
                float p = fmaxf(fmaf((pre[u] - mu) * rs, sv[320 + c], sv[384 + c]), 0.f);
                (&o.x)[u] = (&q4.x)[u] - (&gk4.x)[u] + p;
            }
            *(float4*)&abuf[row * AST + hc4] = o;
            if (hh == 0) {
                s_rx[row] = rx; s_ry[row] = ry; s_rz[row] = rz;
                s_mu[row] = mu; s_rs[row] = rs; s_nb[row] = nb;
            }
        }
        __syncwarp();

        // ---------------- GEMM1 (128x64x64) + per-row LN + relu -> h --------
        {
            float hv[8][8];
            {
                unsigned long long acc[8][4];
                #pragma unroll
                for (int j = 0; j < 4; j++) {
                    unsigned long long bb = pack2(sv[c0 + 2 * j], sv[c0 + 2 * j + 1]);
                    #pragma unroll
                    for (int i = 0; i < 8; i++) acc[i][j] = bb;
                }
                #pragma unroll 2
                for (int k4 = 0; k4 < 64; k4 += 4) {
                    float4 a4[8];
                    #pragma unroll
                    for (int i = 0; i < 8; i++)
                        a4[i] = *(const float4*)&abuf[rofs[i] + k4];
                    #pragma unroll
                    for (int ku = 0; ku < 4; ku++) {
                        int k = k4 + ku;
                        ulonglong2 w0 = *(const ulonglong2*)&wg1s[k * 64 + c0];
                        ulonglong2 w1 = *(const ulonglong2*)&wg1s[k * 64 + c0 + 4];
                        #pragma unroll
                        for (int i = 0; i < 8; i++) {
                            float a = (&a4[i].x)[ku];
                            unsigned long long aa = pack2(a, a);
                            fma2(acc[i][0], aa, w0.x); fma2(acc[i][1], aa, w0.y);
                            fma2(acc[i][2], aa, w1.x); fma2(acc[i][3], aa, w1.y);
                        }
                    }
                }
                #pragma unroll
                for (int i = 0; i < 8; i++) {
                    float2 u0 = unpack2(acc[i][0]), u1 = unpack2(acc[i][1]);
                    float2 u2 = unpack2(acc[i][2]), u3 = unpack2(acc[i][3]);
                    float v[8] = { u0.x, u0.y, u1.x, u1.y, u2.x, u2.y, u3.x, u3.y };
                    float s1 = 0.f, s2 = 0.f;
                    #pragma unroll
                    for (int j = 0; j < 8; j++) { s1 += v[j]; s2 += v[j] * v[j]; }
                    #pragma unroll
                    for (int m = 1; m < 8; m <<= 1) {
                        s1 += __shfl_xor_sync(0xffffffffu, s1, m);
                        s2 += __shfl_xor_sync(0xffffffffu, s2, m);
                    }
                    float mu = s1 * 0.015625f;
                    float rs = rsqrtf(s2 * 0.015625f - mu * mu + EPS);
                    #pragma unroll
                    for (int j = 0; j < 8; j++)
                        hv[i][j] = fmaxf(fmaf((v[j] - mu) * rs, sv[64 + c0 + j], sv[128 + c0 + j]), 0.f);
                }
            }
            __syncwarp();   // warp's attn_in reads complete before overwrite
            #pragma unroll
            for (int i = 0; i < 8; i++) {
                *(float4*)&abuf[rofs[i] + c0]     = make_float4(hv[i][0], hv[i][1], hv[i][2], hv[i][3]);
                *(float4*)&abuf[rofs[i] + c0 + 4] = make_float4(hv[i][4], hv[i][5], hv[i][6], hv[i][7]);
            }
        }
        __syncwarp();

        // ---------------- GEMM2 (w = h @ wg2 + bg2) -> registers ------------
        float wvv[8][8];
        {
            unsigned long long acc[8][4];
            #pragma unroll
            for (int j = 0; j < 4; j++) {
                unsigned long long bb = pack2(sv[192 + c0 + 2 * j], sv[192 + c0 + 2 * j + 1]);
                #pragma unroll
                for (int i = 0; i < 8; i++) acc[i][j] = bb;
            }
            #pragma unroll 2
            for (int k4 = 0; k4 < 64; k4 += 4) {
                float4 a4[8];
                #pragma unroll
                for (int i = 0; i < 8; i++)
                    a4[i] = *(const float4*)&abuf[rofs[i] + k4];
                #pragma unroll
                for (int ku = 0; ku < 4; ku++) {
                    int k = k4 + ku;
                    ulonglong2 w0 = *(const ulonglong2*)&wg2s[k * 64 + c0];
                    ulonglong2 w1 = *(const ulonglong2*)&wg2s[k * 64 + c0 + 4];
                    #pragma unroll
                    for (int i = 0; i < 8; i++) {
                        float a = (&a4[i].x)[ku];
                        unsigned long long aa = pack2(a, a);
                        fma2(acc[i][0], aa, w0.x); fma2(acc[i][1], aa, w0.y);
                        fma2(acc[i][2], aa, w1.x); fma2(acc[i][3], aa, w1.y);
                    }
                }
            }
            #pragma unroll
            for (int i = 0; i < 8; i++) {
                float2 u0 = unpack2(acc[i][0]), u1 = unpack2(acc[i][1]);
                float2 u2 = unpack2(acc[i][2]), u3 = unpack2(acc[i][3]);
                wvv[i][0] = u0.x; wvv[i][1] = u0.y; wvv[i][2] = u1.x; wvv[i][3] = u1.y;
                wvv[i][4] = u2.x; wvv[i][5] = u2.y; wvv[i][6] = u3.x; wvv[i][7] = u3.y;
            }
        }

        // -------- softmax over neighbors + weighted sum of (gv + p) ---------
        #pragma unroll
        for (int ph = 0; ph < 2; ph++) {
            float4 gva[4], gvb[4];
            int rws[4];
            #pragma unroll
            for (int ii = 0; ii < 4; ii++) {
                int row = (rofs[ph * 4 + ii]) / AST;
                rws[ii] = row;
                int nb2 = s_nb[row];
                gva[ii] = *(const float4*)&g_v[(size_t)nb2 * 64 + c0];
                gvb[ii] = *(const float4*)&g_v[(size_t)nb2 * 64 + c0 + 4];
            }
            float mx[8], se[8], wa[8];
            #pragma unroll
            for (int j = 0; j < 8; j++) {
                float m_ = fmaxf(fmaxf(wvv[ph * 4 + 0][j], wvv[ph * 4 + 1][j]),
                                 fmaxf(wvv[ph * 4 + 2][j], wvv[ph * 4 + 3][j]));
                m_ = fmaxf(m_, __shfl_xor_sync(0xffffffffu, m_, 8));
                m_ = fmaxf(m_, __shfl_xor_sync(0xffffffffu, m_, 16));
                mx[j] = m_; se[j] = 0.f; wa[j] = 0.f;
            }
            #pragma unroll
            for (int ii = 0; ii < 4; ii++) {
                int row = rws[ii];
                float rx = s_rx[row], ry = s_ry[row], rz = s_rz[row];
                float mu = s_mu[row], rs = s_rs[row];
                #pragma unroll
                for (int j = 0; j < 8; j++) {
                    int c = c0 + j;
                    float pre = fmaf(rx, sv[512 + c], fmaf(ry, sv[576 + c], fmaf(rz, sv[640 + c], sv[256 + c])));
                    float p = fmaxf(fmaf((pre - mu) * rs, sv[320 + c], sv[384 + c]), 0.f);
                    float gvv = (j < 4) ? (&gva[ii].x)[j] : (&gvb[ii].x)[j - 4];
                    float e = __expf(wvv[ph * 4 + ii][j] - mx[j]);
                    se[j] += e;
                    wa[j] = fmaf(e, gvv + p, wa[j]);
                }
            }
            #pragma unroll
            for (int j = 0; j < 8; j++) {
                se[j] += __shfl_xor_sync(0xffffffffu, se[j], 8);
                se[j] += __shfl_xor_sync(0xffffffffu, se[j], 16);
                wa[j] += __shfl_xor_sync(0xffffffffu, wa[j], 8);
                wa[j] += __shfl_xor_sync(0xffffffffu, wa[j], 16);
            }
            if (rtl == 0) {
                int pl = wid * 2 + ph;
                #pragma unroll
                for (int j = 0; j < 8; j++)
                    s_o[pl * 64 + c0 + j] = wa[j] / se[j];
            }
        }
        __syncthreads();

        // ---------------- epilogue: out = s_o @ wo + bo + residual ----------
        {
            const int c  = t & 63;
            const int pg = t >> 6;           // 0 or 1 -> points pg*4 .. pg*4+3
            float accv[4];
            #pragma unroll
            for (int pp = 0; pp < 4; pp++) accv[pp] = sv[448 + c];
            #pragma unroll 8
            for (int k = 0; k < 64; k++) {
                float w_ = __ldg(&wo[k * 64 + c]);
                #pragma unroll
                for (int pp = 0; pp < 4; pp++)
                    accv[pp] = fmaf(s_o[(pg * 4 + pp) * 64 + k], w_, accv[pp]);
            }
            #pragma unroll
            for (int pp = 0; pp < 4; pp++) {
                int np = pbase + pg * 4 + pp;
                if (np < n) outp[np * 64 + c] = accv[pp] + __ldg(&feat[np * 64 + c]);
            }
        }
        __syncthreads();
    }
}

// ======================= launch =============================================
extern "C" void kernel_launch(void* const* d_in, const int* in_sizes, int n_in,
                              void* d_out, int out_size)
{
    const float* points = (const float*)d_in[0];
    const float* feat   = (const float*)d_in[1];
    const int*   nbr    = (const int*)  d_in[2];
    const float* wq = (const float*)d_in[3];
    const float* bq = (const float*)d_in[4];
    const float* wk = (const float*)d_in[5];
    const float* bk = (const float*)d_in[6];
    const float* wv = (const float*)d_in[7];
    const float* bv = (const float*)d_in[8];
    const float* wp = (const float*)d_in[9];
    const float* bp = (const float*)d_in[10];
    const float* gp = (const float*)d_in[11];
    const float* betap = (const float*)d_in[12];
    const float* wg1 = (const float*)d_in[13];
    const float* bg1 = (const float*)d_in[14];
    const float* gg  = (const float*)d_in[15];
    const float* betag = (const float*)d_in[16];
    const float* wg2 = (const float*)d_in[17];
    const float* bg2 = (const float*)d_in[18];
    const float* wo  = (const float*)d_in[19];
    const float* bo  = (const float*)d_in[20];
    float* outp = (float*)d_out;

    int n = in_sizes[1] / 64;
    if (n > NMAX) n = NMAX;

    cudaFuncSetAttribute(qkv_kernel, cudaFuncAttributeMaxDynamicSharedMemorySize, QK_SMEM_BYTES);
    qkv_kernel<<<(n + 255) / 256, 256, QK_SMEM_BYTES>>>(feat, wq, bq, wk, bk, wv, bv, n);

    cudaFuncSetAttribute(fused_kernel, cudaFuncAttributeMaxDynamicSharedMemorySize, SMEM_BYTES);
    fused_kernel<<<(n + PPB - 1) / PPB, 128, SMEM_BYTES>>>(
        points, feat, nbr,
        wp, bp, gp, betap,
        wg1, bg1, gg, betag,
        wg2, bg2, wo, bo,
        outp, n);
}

// round 6
// speedup vs baseline: 1.2398x; 1.2398x over previous
#include <cuda_runtime.h>
#include <cuda_bf16.h>
#include <cstdint>

#define NMAX 50000
#define EPS  1e-5f
#define PPB  16          // points per block (2 sub-batches of 8)
#define WST  68          // logits buffer row stride (floats)
#define RSTB 144         // bf16 tile row stride in BYTES (64 bf16 data + pad)

// ---------------- scratch (static device arrays: allocation-free) ----------
__device__ float g_q[NMAX * 64];
__device__ float g_k[NMAX * 64];
__device__ float g_v[NMAX * 64];

// ---------------- packed f32x2 helpers (qkv kernel) -------------------------
__device__ __forceinline__ unsigned long long pack2(float x, float y) {
    unsigned long long r;
    asm("mov.b64 %0,{%1,%2};" : "=l"(r) : "f"(x), "f"(y));
    return r;
}
__device__ __forceinline__ void fma2(unsigned long long& d, unsigned long long a, unsigned long long b) {
    asm("fma.rn.f32x2 %0,%1,%2,%0;" : "+l"(d) : "l"(a), "l"(b));
}
__device__ __forceinline__ float2 unpack2(unsigned long long v) {
    float2 f;
    asm("mov.b64 {%0,%1},%2;" : "=f"(f.x), "=f"(f.y) : "l"(v));
    return f;
}

// ---------------- mma / ldmatrix helpers ------------------------------------
__device__ __forceinline__ uint32_t smem_u32(const void* p) {
    uint32_t a;
    asm("{ .reg .u64 t; cvta.to.shared.u64 t, %1; cvt.u32.u64 %0, t; }" : "=r"(a) : "l"(p));
    return a;
}
__device__ __forceinline__ void ldsm4(uint32_t* r, uint32_t addr) {
    asm volatile("ldmatrix.sync.aligned.m8n8.x4.shared.b16 {%0,%1,%2,%3},[%4];"
        : "=r"(r[0]), "=r"(r[1]), "=r"(r[2]), "=r"(r[3]) : "r"(addr));
}
__device__ __forceinline__ void ldsm2t(uint32_t* r, uint32_t addr) {
    asm volatile("ldmatrix.sync.aligned.m8n8.x2.trans.shared.b16 {%0,%1},[%2];"
        : "=r"(r[0]), "=r"(r[1]) : "r"(addr));
}
__device__ __forceinline__ void mma_bf16(float* c, const uint32_t* a, const uint32_t* b) {
    asm volatile("mma.sync.aligned.m16n8k16.row.col.f32.bf16.bf16.f32 "
        "{%0,%1,%2,%3},{%4,%5,%6,%7},{%8,%9},{%0,%1,%2,%3};"
        : "+f"(c[0]), "+f"(c[1]), "+f"(c[2]), "+f"(c[3])
        : "r"(a[0]), "r"(a[1]), "r"(a[2]), "r"(a[3]), "r"(b[0]), "r"(b[1]));
}
__device__ __forceinline__ void split2(float x0, float x1, uint32_t& hi, uint32_t& lo) {
    __nv_bfloat162 h = __floats2bfloat162_rn(x0, x1);
    hi = *(uint32_t*)&h;
    __nv_bfloat162 l = __floats2bfloat162_rn(x0 - __bfloat162float(h.x),
                                             x1 - __bfloat162float(h.y));
    lo = *(uint32_t*)&l;
}
__device__ __forceinline__ void split8(const float* o, uint4& h4, uint4& l4) {
    split2(o[0], o[1], h4.x, l4.x);
    split2(o[2], o[3], h4.y, l4.y);
    split2(o[4], o[5], h4.z, l4.z);
    split2(o[6], o[7], h4.w, l4.w);
}

// ======================= kernel 1: q/k/v projections (round-3) ==============
__global__ __launch_bounds__(256) void qkv_kernel(
    const float* __restrict__ feat,
    const float* __restrict__ wq, const float* __restrict__ bq,
    const float* __restrict__ wk, const float* __restrict__ bk,
    const float* __restrict__ wv, const float* __restrict__ bv,
    int n)
{
    __shared__ float Fs[64 * 65];
    __shared__ float Ws[64 * 64];
    const int t = threadIdx.x;
    const int row0 = blockIdx.x * 64;

    for (int i = t; i < 64 * 16; i += 256) {
        int r = i >> 4;
        int c4 = (i & 15) * 4;
        float4 f = make_float4(0.f, 0.f, 0.f, 0.f);
        if (row0 + r < n) f = *(const float4*)&feat[(row0 + r) * 64 + c4];
        Fs[r * 65 + c4 + 0] = f.x; Fs[r * 65 + c4 + 1] = f.y;
        Fs[r * 65 + c4 + 2] = f.z; Fs[r * 65 + c4 + 3] = f.w;
    }

    const float* Wm[3] = { wq, wk, wv };
    const float* Bm[3] = { bq, bk, bv };
    float* Om[3] = { g_q, g_k, g_v };

    const int cg = t & 7;
    const int r0 = t >> 3;
    const int c0 = cg * 8;

    for (int m = 0; m < 3; m++) {
        __syncthreads();
        for (int i = t; i < 1024; i += 256)
            ((float4*)Ws)[i] = ((const float4*)Wm[m])[i];
        __syncthreads();

        unsigned long long acc[2][4];
        {
            const float* b = Bm[m];
            #pragma unroll
            for (int h = 0; h < 4; h++) {
                unsigned long long bb = pack2(__ldg(&b[c0 + 2 * h]), __ldg(&b[c0 + 2 * h + 1]));
                acc[0][h] = bb; acc[1][h] = bb;
            }
        }
        #pragma unroll 16
        for (int k = 0; k < 64; k++) {
            float a0f = Fs[r0 * 65 + k];
            float a1f = Fs[(r0 + 32) * 65 + k];
            unsigned long long a0 = pack2(a0f, a0f);
            unsigned long long a1 = pack2(a1f, a1f);
            const ulonglong2* w = (const ulonglong2*)&Ws[k * 64 + c0];
            ulonglong2 w0 = w[0], w1 = w[1];
            fma2(acc[0][0], a0, w0.x); fma2(acc[0][1], a0, w0.y);
            fma2(acc[0][2], a0, w1.x); fma2(acc[0][3], a0, w1.y);
            fma2(acc[1][0], a1, w0.x); fma2(acc[1][1], a1, w0.y);
            fma2(acc[1][2], a1, w1.x); fma2(acc[1][3], a1, w1.y);
        }
        #pragma unroll
        for (int rr = 0; rr < 2; rr++) {
            int gr = row0 + r0 + rr * 32;
            if (gr < n) {
                float2 p0 = unpack2(acc[rr][0]);
                float2 p1 = unpack2(acc[rr][1]);
                float2 p2 = unpack2(acc[rr][2]);
                float2 p3 = unpack2(acc[rr][3]);
                *(float4*)&Om[m][gr * 64 + c0]     = make_float4(p0.x, p0.y, p1.x, p1.y);
                *(float4*)&Om[m][gr * 64 + c0 + 4] = make_float4(p2.x, p2.y, p3.x, p3.y);
            }
        }
    }
}

// ======================= kernel 2: bf16 HMMA fused kernel ===================
// SMEM byte layout:
#define OFF_W1H  0
#define OFF_W1L  9216
#define OFF_W2H  18432
#define OFF_W2L  27648
#define OFF_AH   36864         // A tile hi: 128 rows x RSTB
#define OFF_AL   55296         // A tile lo
#define OFF_WBUF 36864         // logits overlay on A (128*WST*4 = 34816 <= 36864)
#define OFF_STAT 73728         // rx,ry,rz,mu,rs (5*512) + nb (512)
#define OFF_SO   76800         // 512 floats
#define OFF_SV   78848         // 768 floats
#define SMEM_BYTES 81920

template<bool SYNC_AFTER_A>
__device__ __forceinline__ void gemm_stage(
    float acc[2][8][4], const uint32_t aoff[2][4],
    uint32_t abaseH, uint32_t abaseL,
    uint32_t wbaseH, uint32_t wbaseL, uint32_t brow)
{
    uint32_t Ah[2][4][4], Al[2][4][4];
    #pragma unroll
    for (int m = 0; m < 2; m++)
        #pragma unroll
        for (int k = 0; k < 4; k++) {
            ldsm4(Ah[m][k], abaseH + aoff[m][k]);
            ldsm4(Al[m][k], abaseL + aoff[m][k]);
        }
    if (SYNC_AFTER_A) __syncthreads();
    #pragma unroll
    for (int m = 0; m < 2; m++)
        #pragma unroll
        for (int nt = 0; nt < 8; nt++)
            #pragma unroll
            for (int i = 0; i < 4; i++) acc[m][nt][i] = 0.f;
    #pragma unroll
    for (int nt = 0; nt < 8; nt++) {
        uint32_t bh[4][2], bl[4][2];
        #pragma unroll
        for (int k = 0; k < 4; k++) ldsm2t(bh[k], wbaseH + (uint32_t)(k * 16) * RSTB + brow + nt * 16);
        #pragma unroll
        for (int m = 0; m < 2; m++)
            #pragma unroll
            for (int k = 0; k < 4; k++) mma_bf16(acc[m][nt], Ah[m][k], bh[k]);
        #pragma unroll
        for (int m = 0; m < 2; m++)
            #pragma unroll
            for (int k = 0; k < 4; k++) mma_bf16(acc[m][nt], Al[m][k], bh[k]);
        #pragma unroll
        for (int k = 0; k < 4; k++) ldsm2t(bl[k], wbaseL + (uint32_t)(k * 16) * RSTB + brow + nt * 16);
        #pragma unroll
        for (int m = 0; m < 2; m++)
            #pragma unroll
            for (int k = 0; k < 4; k++) mma_bf16(acc[m][nt], Ah[m][k], bl[k]);
    }
}

__global__ __launch_bounds__(128, 2) void fused_kernel(
    const float* __restrict__ points,
    const float* __restrict__ feat,
    const int*   __restrict__ nbr,
    const float* __restrict__ wp,  const float* __restrict__ bp,
    const float* __restrict__ gp,  const float* __restrict__ betap,
    const float* __restrict__ wg1, const float* __restrict__ bg1,
    const float* __restrict__ gg,  const float* __restrict__ betag,
    const float* __restrict__ wg2, const float* __restrict__ bg2,
    const float* __restrict__ wo,  const float* __restrict__ bo,
    float* __restrict__ outp, int n)
{
    extern __shared__ char smb[];
    float* wbuf = (float*)(smb + OFF_WBUF);
    float* s_rx = (float*)(smb + OFF_STAT);
    float* s_ry = s_rx + 128;
    float* s_rz = s_ry + 128;
    float* s_mu = s_rz + 128;
    float* s_rs = s_mu + 128;
    int*   s_nb = (int*)(s_rs + 128);
    float* s_o  = (float*)(smb + OFF_SO);
    float* sv   = (float*)(smb + OFF_SV);
    // sv: [0]=bg1 [64]=gg [128]=betag [192]=bg2 [256]=bp [320]=gp [384]=betap
    //     [448]=bo [512..704)=wp rows

    const int t   = threadIdx.x;
    const int wid = t >> 5;
    const int lid = t & 31;
    const uint32_t sbase = smem_u32(smb);

    // ---- small vectors ----
    if (t < 64) {
        sv[t]       = bg1[t];   sv[64 + t]  = gg[t];      sv[128 + t] = betag[t];
        sv[192 + t] = bg2[t];   sv[256 + t] = bp[t];      sv[320 + t] = gp[t];
        sv[384 + t] = betap[t]; sv[448 + t] = bo[t];
        sv[512 + t] = wp[t];    sv[576 + t] = wp[64 + t]; sv[640 + t] = wp[128 + t];
    }

    // ---- stage weights: bf16 hi/lo split, row-major [k][n], stride RSTB ----
    {
        const int rw = t >> 1;            // weight row (k) 0..63
        const int hf = (t & 1) * 32;      // col half
        #pragma unroll
        for (int m = 0; m < 2; m++) {
            const float* w = m ? wg2 : wg1;
            char* dH = smb + (m ? OFF_W2H : OFF_W1H) + rw * RSTB;
            char* dL = smb + (m ? OFF_W2L : OFF_W1L) + rw * RSTB;
            #pragma unroll
            for (int c8 = 0; c8 < 32; c8 += 8) {
                int c = hf + c8;
                float o[8];
                float4 f0 = __ldg((const float4*)&w[rw * 64 + c]);
                float4 f1 = __ldg((const float4*)&w[rw * 64 + c + 4]);
                o[0]=f0.x; o[1]=f0.y; o[2]=f0.z; o[3]=f0.w;
                o[4]=f1.x; o[5]=f1.y; o[6]=f1.z; o[7]=f1.w;
                uint4 h4, l4;
                split8(o, h4, l4);
                *(uint4*)(dH + c * 2) = h4;
                *(uint4*)(dL + c * 2) = l4;
            }
        }
    }
    __syncthreads();

    // fragment geometry
    const int q  = lid >> 3;
    const int rl = lid & 7;
    uint32_t aoff[2][4];
    #pragma unroll
    for (int m = 0; m < 2; m++)
        #pragma unroll
        for (int k = 0; k < 4; k++)
            aoff[m][k] = (uint32_t)(wid * 32 + m * 16 + rl + (q & 1) * 8) * RSTB
                       + (uint32_t)(k * 32) + (uint32_t)((q >> 1) * 16);
    const uint32_t brow = (uint32_t)(lid & 15) * RSTB;
    const int dr = lid >> 2;          // fragment row within 8
    const int dc = (lid & 3) * 2;     // fragment col pair base
    const int rtl = (t >> 3) & 3;
    const int cg  = t & 7;
    const int c0  = cg * 8;

    float acc[2][8][4];

    for (int b = 0; b < 2; b++) {
        const int pbase = blockIdx.x * PPB + b * 8;

        // ---------------- phase A: attn_in rows -> A tile (hi/lo bf16) ------
        {
            const int r   = t;
            const int np  = pbase + (r >> 4);
            const int jn  = r & 15;
            const int npc = (np < n) ? np : 0;
            const int nb  = __ldg(&nbr[npc * 16 + jn]);

            float rx = __ldg(&points[nb * 3 + 0]) - __ldg(&points[npc * 3 + 0]);
            float ry = __ldg(&points[nb * 3 + 1]) - __ldg(&points[npc * 3 + 1]);
            float rz = __ldg(&points[nb * 3 + 2]) - __ldg(&points[npc * 3 + 2]);

            float s1 = 0.f, s2 = 0.f;
            #pragma unroll
            for (int c = 0; c < 64; c++) {
                float pre = fmaf(rx, sv[512 + c], fmaf(ry, sv[576 + c], fmaf(rz, sv[640 + c], sv[256 + c])));
                s1 += pre; s2 += pre * pre;
            }
            float mu = s1 * 0.015625f;
            float rs = rsqrtf(s2 * 0.015625f - mu * mu + EPS);
            s_rx[r] = rx; s_ry[r] = ry; s_rz[r] = rz;
            s_mu[r] = mu; s_rs[r] = rs; s_nb[r] = nb;

            const float* gkp = &g_k[(size_t)nb * 64];
            const float* qp  = &g_q[(size_t)npc * 64];
            char* pH = smb + OFF_AH + r * RSTB;
            char* pL = smb + OFF_AL + r * RSTB;
            #pragma unroll
            for (int c8 = 0; c8 < 64; c8 += 8) {
                float4 qa = *(const float4*)&qp[c8];
                float4 qb = *(const float4*)&qp[c8 + 4];
                float4 ka = *(const float4*)&gkp[c8];
                float4 kb = *(const float4*)&gkp[c8 + 4];
                float o[8];
                #pragma unroll
                for (int u = 0; u < 8; u++) {
                    int c = c8 + u;
                    float pre = fmaf(rx, sv[512 + c], fmaf(ry, sv[576 + c], fmaf(rz, sv[640 + c], sv[256 + c])));
                    float p = fmaxf(fmaf((pre - mu) * rs, sv[320 + c], sv[384 + c]), 0.f);
                    float qv = (u < 4) ? (&qa.x)[u] : (&qb.x)[u - 4];
                    float kv = (u < 4) ? (&ka.x)[u] : (&kb.x)[u - 4];
                    o[u] = qv - kv + p;
                }
                uint4 h4, l4;
                split8(o, h4, l4);
                *(uint4*)(pH + c8 * 2) = h4;
                *(uint4*)(pL + c8 * 2) = l4;
            }
        }
        __syncwarp();

        // ---------------- GEMM1 + bias + per-row LN + relu -> h -------------
        gemm_stage<false>(acc, aoff, sbase + OFF_AH, sbase + OFF_AL,
                          sbase + OFF_W1H, sbase + OFF_W1L, brow);
        #pragma unroll
        for (int m = 0; m < 2; m++) {
            float va[16], vb[16];
            float s1a = 0.f, s2a = 0.f, s1b = 0.f, s2b = 0.f;
            #pragma unroll
            for (int nt = 0; nt < 8; nt++) {
                int c = nt * 8 + dc;
                float x0 = acc[m][nt][0] + sv[c];
                float x1 = acc[m][nt][1] + sv[c + 1];
                float y0 = acc[m][nt][2] + sv[c];
                float y1 = acc[m][nt][3] + sv[c + 1];
                va[nt * 2] = x0; va[nt * 2 + 1] = x1;
                vb[nt * 2] = y0; vb[nt * 2 + 1] = y1;
                s1a += x0 + x1; s2a += fmaf(x0, x0, x1 * x1);
                s1b += y0 + y1; s2b += fmaf(y0, y0, y1 * y1);
            }
            #pragma unroll
            for (int mk = 1; mk < 4; mk <<= 1) {
                s1a += __shfl_xor_sync(0xffffffffu, s1a, mk);
                s2a += __shfl_xor_sync(0xffffffffu, s2a, mk);
                s1b += __shfl_xor_sync(0xffffffffu, s1b, mk);
                s2b += __shfl_xor_sync(0xffffffffu, s2b, mk);
            }
            float mua = s1a * 0.015625f;
            float rsa = rsqrtf(s2a * 0.015625f - mua * mua + EPS);
            float mub = s1b * 0.015625f;
            float rsb = rsqrtf(s2b * 0.015625f - mub * mub + EPS);
            int rowA = wid * 32 + m * 16 + dr;
            char* pHa = smb + OFF_AH + rowA * RSTB;
            char* pLa = smb + OFF_AL + rowA * RSTB;
            char* pHb = pHa + 8 * RSTB;
            char* pLb = pLa + 8 * RSTB;
            #pragma unroll
            for (int nt = 0; nt < 8; nt++) {
                int c = nt * 8 + dc;
                float g0 = sv[64 + c], g1 = sv[64 + c + 1];
                float e0 = sv[128 + c], e1 = sv[128 + c + 1];
                float h0 = fmaxf(fmaf((va[nt*2]   - mua) * rsa, g0, e0), 0.f);
                float h1 = fmaxf(fmaf((va[nt*2+1] - mua) * rsa, g1, e1), 0.f);
                float h2 = fmaxf(fmaf((vb[nt*2]   - mub) * rsb, g0, e0), 0.f);
                float h3 = fmaxf(fmaf((vb[nt*2+1] - mub) * rsb, g1, e1), 0.f);
                uint32_t hw, lw;
                split2(h0, h1, hw, lw);
                *(uint32_t*)(pHa + c * 2) = hw;
                *(uint32_t*)(pLa + c * 2) = lw;
                split2(h2, h3, hw, lw);
                *(uint32_t*)(pHb + c * 2) = hw;
                *(uint32_t*)(pLb + c * 2) = lw;
            }
        }
        __syncwarp();

        // ---------------- GEMM2 (sync inside after A preload) ---------------
        gemm_stage<true>(acc, aoff, sbase + OFF_AH, sbase + OFF_AL,
                         sbase + OFF_W2H, sbase + OFF_W2L, brow);

        // ---------------- logits (+bg2) -> wbuf overlay ---------------------
        #pragma unroll
        for (int m = 0; m < 2; m++) {
            int rowA = wid * 32 + m * 16 + dr;
            int rowB = rowA + 8;
            #pragma unroll
            for (int nt = 0; nt < 8; nt++) {
                int c = nt * 8 + dc;
                wbuf[rowA * WST + c]     = acc[m][nt][0] + sv[192 + c];
                wbuf[rowA * WST + c + 1] = acc[m][nt][1] + sv[192 + c + 1];
                wbuf[rowB * WST + c]     = acc[m][nt][2] + sv[192 + c];
                wbuf[rowB * WST + c + 1] = acc[m][nt][3] + sv[192 + c + 1];
            }
        }
        __syncwarp();

        // -------- softmax over neighbors + weighted sum of (gv + p) ---------
        #pragma unroll
        for (int ph = 0; ph < 2; ph++) {
            float lw[4][8];
            float4 gva[4], gvb[4];
            int rws[4];
            #pragma unroll
            for (int ii = 0; ii < 4; ii++) {
                int row = wid * 32 + ph * 16 + ii * 4 + rtl;
                rws[ii] = row;
                int nb2 = s_nb[row];
                gva[ii] = *(const float4*)&g_v[(size_t)nb2 * 64 + c0];
                gvb[ii] = *(const float4*)&g_v[(size_t)nb2 * 64 + c0 + 4];
                #pragma unroll
                for (int j = 0; j < 8; j++) lw[ii][j] = wbuf[row * WST + c0 + j];
            }
            float mx[8], se[8], wa[8];
            #pragma unroll
            for (int j = 0; j < 8; j++) {
                float m_ = fmaxf(fmaxf(lw[0][j], lw[1][j]), fmaxf(lw[2][j], lw[3][j]));
                m_ = fmaxf(m_, __shfl_xor_sync(0xffffffffu, m_, 8));
                m_ = fmaxf(m_, __shfl_xor_sync(0xffffffffu, m_, 16));
                mx[j] = m_; se[j] = 0.f; wa[j] = 0.f;
            }
            #pragma unroll
            for (int ii = 0; ii < 4; ii++) {
                int row = rws[ii];
                float rx = s_rx[row], ry = s_ry[row], rz = s_rz[row];
                float mu = s_mu[row], rs = s_rs[row];
                #pragma unroll
                for (int j = 0; j < 8; j++) {
                    int c = c0 + j;
                    float pre = fmaf(rx, sv[512 + c], fmaf(ry, sv[576 + c], fmaf(rz, sv[640 + c], sv[256 + c])));
                    float p = fmaxf(fmaf((pre - mu) * rs, sv[320 + c], sv[384 + c]), 0.f);
                    float gvv = (j < 4) ? (&gva[ii].x)[j] : (&gvb[ii].x)[j - 4];
                    float e = __expf(lw[ii][j] - mx[j]);
                    se[j] += e;
                    wa[j] = fmaf(e, gvv + p, wa[j]);
                }
            }
            #pragma unroll
            for (int j = 0; j < 8; j++) {
                se[j] += __shfl_xor_sync(0xffffffffu, se[j], 8);
                se[j] += __shfl_xor_sync(0xffffffffu, se[j], 16);
                wa[j] += __shfl_xor_sync(0xffffffffu, wa[j], 8);
                wa[j] += __shfl_xor_sync(0xffffffffu, wa[j], 16);
            }
            if (rtl == 0) {
                int pl = wid * 2 + ph;
                #pragma unroll
                for (int j = 0; j < 8; j++)
                    s_o[pl * 64 + c0 + j] = wa[j] / se[j];
            }
        }
        __syncthreads();

        // ---------------- epilogue: out = s_o @ wo + bo + residual ----------
        {
            const int c  = t & 63;
            const int pg = t >> 6;
            float accv[4];
            #pragma unroll
            for (int pp = 0; pp < 4; pp++) accv[pp] = sv[448 + c];
            #pragma unroll 8
            for (int k = 0; k < 64; k++) {
                float w_ = __ldg(&wo[k * 64 + c]);
                #pragma unroll
                for (int pp = 0; pp < 4; pp++)
                    accv[pp] = fmaf(s_o[(pg * 4 + pp) * 64 + k], w_, accv[pp]);
            }
            #pragma unroll
            for (int pp = 0; pp < 4; pp++) {
                int np = pbase + pg * 4 + pp;
                if (np < n) outp[np * 64 + c] = accv[pp] + __ldg(&feat[np * 64 + c]);
            }
        }
        __syncthreads();
    }
}

// ======================= launch =============================================
extern "C" void kernel_launch(void* const* d_in, const int* in_sizes, int n_in,
                              void* d_out, int out_size)
{
    const float* points = (const float*)d_in[0];
    const float* feat   = (const float*)d_in[1];
    const int*   nbr    = (const int*)  d_in[2];
    const float* wq = (const float*)d_in[3];
    const float* bq = (const float*)d_in[4];
    const float* wk = (const float*)d_in[5];
    const float* bk = (const float*)d_in[6];
    const float* wv = (const float*)d_in[7];
    const float* bv = (const float*)d_in[8];
    const float* wp = (const float*)d_in[9];
    const float* bp = (const float*)d_in[10];
    const float* gp = (const float*)d_in[11];
    const float* betap = (const float*)d_in[12];
    const float* wg1 = (const float*)d_in[13];
    const float* bg1 = (const float*)d_in[14];
    const float* gg  = (const float*)d_in[15];
    const float* betag = (const float*)d_in[16];
    const float* wg2 = (const float*)d_in[17];
    const float* bg2 = (const float*)d_in[18];
    const float* wo  = (const float*)d_in[19];
    const float* bo  = (const float*)d_in[20];
    float* outp = (float*)d_out;

    int n = in_sizes[1] / 64;
    if (n > NMAX) n = NMAX;

    qkv_kernel<<<(n + 63) / 64, 256>>>(feat, wq, bq, wk, bk, wv, bv, n);

    cudaFuncSetAttribute(fused_kernel, cudaFuncAttributeMaxDynamicSharedMemorySize, SMEM_BYTES);
    fused_kernel<<<(n + PPB - 1) / PPB, 128, SMEM_BYTES>>>(
        points, feat, nbr,
        wp, bp, gp, betap,
        wg1, bg1, gg, betag,
        wg2, bg2, wo, bo,
        outp, n);
}